// round 3
// baseline (speedup 1.0000x reference)
#include <cuda_runtime.h>
#include <math.h>

#define NSTEPS 8192
#define NNODES 4096
#define SG 256
#define NROW 2048
#define DFF 2048
#define H1DIM 512

// scratch: h_t for every step (pure function of recurrence, consumed by sampler)
__device__ float g_h_all[NSTEPS * SG];

__device__ __forceinline__ float warp_reduce(float v) {
#pragma unroll
    for (int o = 16; o; o >>= 1) v += __shfl_xor_sync(0xffffffffu, v, o);
    return v;
}

// dot of one weight row (global, length C, C%128==0... actually C%4==0 and C>=128)
// with x (smem, 16B aligned). Whole warp participates; result valid on all lanes.
template <int C>
__device__ __forceinline__ float row_dot(const float* __restrict__ W,
                                         const float* __restrict__ x, int lane) {
    const float4* __restrict__ W4 = reinterpret_cast<const float4*>(W);
    const float4* __restrict__ x4 = reinterpret_cast<const float4*>(x);
    float s = 0.f;
#pragma unroll
    for (int c = 0; c < C / 4; c += 32) {
        float4 w = W4[c + lane];
        float4 xv = x4[c + lane];
        s += w.x * xv.x + w.y * xv.y + w.z * xv.z + w.w * xv.w;
    }
    return warp_reduce(s);
}

// LayerNorm over 256 elements, two-pass (matches ((x-mu)^2).mean()).
// y: input smem[256], out: smem[256] (may differ), red: smem[2]. All threads call.
__device__ __forceinline__ void layernorm256(const float* __restrict__ y,
                                             float* __restrict__ out,
                                             const float* __restrict__ gma,
                                             const float* __restrict__ bta,
                                             int tid, float* red) {
    int w = tid >> 5, lane = tid & 31;
    if (w == 0) {
        float s = 0.f;
#pragma unroll
        for (int i = 0; i < 8; ++i) s += y[lane + 32 * i];
        s = warp_reduce(s);
        if (lane == 0) red[0] = s * (1.f / 256.f);
    }
    __syncthreads();
    float mu = red[0];
    if (w == 0) {
        float s = 0.f;
#pragma unroll
        for (int i = 0; i < 8; ++i) {
            float d = y[lane + 32 * i] - mu;
            s += d * d;
        }
        s = warp_reduce(s);
        if (lane == 0) red[1] = 1.f / sqrtf(s * (1.f / 256.f) + 1e-5f);
    }
    __syncthreads();
    float inv = red[1];
    if (tid < 256) out[tid] = (y[tid] - mu) * inv * gma[tid] + bta[tid];
    __syncthreads();
}

__global__ void __launch_bounds__(1024, 1) seq_kernel(
    const float* __restrict__ gnn,
    const float* __restrict__ W1, const float* __restrict__ b1,
    const float* __restrict__ W2, const float* __restrict__ b2,
    const float* __restrict__ Wg, const float* __restrict__ bg,
    const float* __restrict__ Wv, const float* __restrict__ bv,
    const float* __restrict__ Wo, const float* __restrict__ bo,
    const float* __restrict__ Wf1, const float* __restrict__ bf1,
    const float* __restrict__ Wf2, const float* __restrict__ bf2,
    const float* __restrict__ ln1g, const float* __restrict__ ln1b,
    const float* __restrict__ ln2g, const float* __restrict__ ln2b) {
    __shared__ __align__(16) float cat[H1DIM];  // [m(256); g(256)] -- g lives here
    __shared__ __align__(16) float h1[H1DIM];
    __shared__ __align__(16) float h[SG];
    __shared__ __align__(16) float gnew[SG];
    __shared__ __align__(16) float vv[SG];
    __shared__ __align__(16) float y[SG];
    __shared__ __align__(16) float x[SG];
    __shared__ __align__(16) float ff1[DFF];
    __shared__ float red[2];

    int tid = threadIdx.x;
    int w = tid >> 5, lane = tid & 31;

    if (tid < 256) cat[256 + tid] = 0.f;  // g0 = 0
    __syncthreads();

    for (int t = 0; t < NSTEPS; ++t) {
        // m = m_seq[t] = gnn_embeds[t % 4096]
        if (tid < 256) cat[tid] = gnn[(size_t)(t & (NNODES - 1)) * SG + tid];
        __syncthreads();

        // h1 = relu(W1 @ [m;g] + b1)    (512 rows x 512 cols)
        for (int r = w; r < H1DIM; r += 32) {
            float s = row_dot<H1DIM>(W1 + (size_t)r * H1DIM, cat, lane);
            if (lane == 0) h1[r] = fmaxf(s + b1[r], 0.f);
        }
        __syncthreads();

        // h = W2 @ h1 + b2              (256 x 512)
        for (int r = w; r < SG; r += 32) {
            float s = row_dot<H1DIM>(W2 + (size_t)r * H1DIM, h1, lane);
            if (lane == 0) h[r] = s + b2[r];
        }
        __syncthreads();

        // persist h_t for the parallel sampler
        if (tid < 256) g_h_all[(size_t)t * SG + tid] = h[tid];

        // g_new = Wg @ h + bg           (256 x 256)
        for (int r = w; r < SG; r += 32) {
            float s = row_dot<SG>(Wg + (size_t)r * SG, h, lane);
            if (lane == 0) gnew[r] = s + bg[r];
        }
        __syncthreads();

        // vv = Wv @ g_new + bv
        for (int r = w; r < SG; r += 32) {
            float s = row_dot<SG>(Wv + (size_t)r * SG, gnew, lane);
            if (lane == 0) vv[r] = s + bv[r];
        }
        __syncthreads();

        // y = g_new + (Wo @ vv + bo)
        for (int r = w; r < SG; r += 32) {
            float s = row_dot<SG>(Wo + (size_t)r * SG, vv, lane);
            if (lane == 0) y[r] = gnew[r] + (s + bo[r]);
        }
        __syncthreads();

        // x = LN1(y)
        layernorm256(y, x, ln1g, ln1b, tid, red);

        // ff1 = relu(Wf1 @ x + bf1)     (2048 x 256)
        for (int r = w; r < DFF; r += 32) {
            float s = row_dot<SG>(Wf1 + (size_t)r * SG, x, lane);
            if (lane == 0) ff1[r] = fmaxf(s + bf1[r], 0.f);
        }
        __syncthreads();

        // y = x + Wf2 @ ff1 + bf2       (256 x 2048)
        for (int r = w; r < SG; r += 32) {
            float s = row_dot<DFF>(Wf2 + (size_t)r * DFF, ff1, lane);
            if (lane == 0) y[r] = x[r] + (s + bf2[r]);
        }
        __syncthreads();

        // g = LN2(y) -> stored into cat[256..511] for next step
        layernorm256(y, cat + 256, ln2g, ln2b, tid, red);
    }
}

// One block per timestep t: probs = sigmoid(Wr @ h_t + br), per-try counts,
// first-valid-try selection, emit 0/1 row.
__global__ void __launch_bounds__(256) sample_kernel(
    const float* __restrict__ u,
    const float* __restrict__ Wr, const float* __restrict__ br,
    float* __restrict__ out) {
    __shared__ __align__(16) float h[SG];
    __shared__ float probs[NROW];
    __shared__ int cnt[4];
    __shared__ int sel;

    int t = blockIdx.x;
    int tid = threadIdx.x, w = tid >> 5, lane = tid & 31;

    h[tid] = g_h_all[(size_t)t * SG + tid];
    if (tid < 4) cnt[tid] = 0;
    __syncthreads();

    // probs (warp-per-row), sigmoid branched like jax.nn.sigmoid
    for (int r = w; r < NROW; r += 8) {
        float s = row_dot<SG>(Wr + (size_t)r * SG, h, lane);
        if (lane == 0) {
            float z = s + br[r];
            float p;
            if (z >= 0.f) {
                p = 1.f / (1.f + expf(-z));
            } else {
                float e = expf(z);
                p = e / (1.f + e);
            }
            probs[r] = p;
        }
    }
    __syncthreads();

    const float* __restrict__ ut = u + (size_t)t * 4 * NROW;

    int c[4] = {0, 0, 0, 0};
#pragma unroll
    for (int k = 0; k < 4; ++k) {
#pragma unroll
        for (int i = 0; i < 8; ++i) {
            int n = tid + 256 * i;
            c[k] += (ut[k * NROW + n] < probs[n]) ? 1 : 0;
        }
    }
#pragma unroll
    for (int k = 0; k < 4; ++k) {
        int s = c[k];
#pragma unroll
        for (int o = 16; o; o >>= 1) s += __shfl_xor_sync(0xffffffffu, s, o);
        if (lane == 0) atomicAdd(&cnt[k], s);
    }
    __syncthreads();

    if (tid == 0) {
        int idx = 0;
        for (int k = 3; k >= 0; --k) {
            int ck = cnt[k];
            bool valid = (ck == 0) || (ck >= 2 && ck <= 6);
            if (valid) idx = k;  // ends at smallest valid k (argmax of bool = first True)
        }
        sel = idx;
    }
    __syncthreads();

    int idx = sel;
#pragma unroll
    for (int i = 0; i < 8; ++i) {
        int n = tid + 256 * i;
        out[(size_t)t * NROW + n] = (ut[idx * NROW + n] < probs[n]) ? 1.f : 0.f;
    }
}

extern "C" void kernel_launch(void* const* d_in, const int* in_sizes, int n_in,
                              void* d_out, int out_size) {
    (void)in_sizes; (void)n_in; (void)out_size;
    const float* gnn  = (const float*)d_in[0];
    // d_in[1] = b (unused dummy)
    const float* u    = (const float*)d_in[2];
    const float* W1   = (const float*)d_in[3];
    const float* b1   = (const float*)d_in[4];
    const float* W2   = (const float*)d_in[5];
    const float* b2   = (const float*)d_in[6];
    const float* Wr   = (const float*)d_in[7];
    const float* br   = (const float*)d_in[8];
    const float* Wg   = (const float*)d_in[9];
    const float* bg   = (const float*)d_in[10];
    const float* Wv   = (const float*)d_in[11];
    const float* bv   = (const float*)d_in[12];
    const float* Wo   = (const float*)d_in[13];
    const float* bo   = (const float*)d_in[14];
    const float* Wf1  = (const float*)d_in[15];
    const float* bf1  = (const float*)d_in[16];
    const float* Wf2  = (const float*)d_in[17];
    const float* bf2  = (const float*)d_in[18];
    const float* ln1g = (const float*)d_in[19];
    const float* ln1b = (const float*)d_in[20];
    const float* ln2g = (const float*)d_in[21];
    const float* ln2b = (const float*)d_in[22];

    seq_kernel<<<1, 1024>>>(gnn, W1, b1, W2, b2, Wg, bg, Wv, bv, Wo, bo,
                            Wf1, bf1, Wf2, bf2, ln1g, ln1b, ln2g, ln2b);
    sample_kernel<<<NSTEPS, 256>>>(u, Wr, br, (float*)d_out);
}

// round 4
// speedup vs baseline: 4.2424x; 4.2424x over previous
#include <cuda_runtime.h>
#include <math.h>

#define NSTEPS 8192
#define NNODES 4096
#define SG 256
#define NROW 2048
#define DFF 2048
#define H1DIM 512

// h_t for every step (pure function of recurrence, consumed by sampler),
// doubles as the cluster broadcast buffer for h.
__device__ float g_h_all[NSTEPS * SG];
// cluster broadcast buffers (one step in flight at a time)
__device__ float g_h1[H1DIM];
__device__ float g_gnew[SG];
__device__ float g_vv[SG];
__device__ float g_y1[SG];
__device__ float g_ff1[DFF];
__device__ float g_y2[SG];

#define CLU_SYNC()                                                        \
    do {                                                                  \
        asm volatile("barrier.cluster.arrive.aligned;" ::: "memory");    \
        asm volatile("barrier.cluster.wait.aligned;" ::: "memory");      \
    } while (0)

__device__ __forceinline__ float warp_reduce(float v) {
#pragma unroll
    for (int o = 16; o; o >>= 1) v += __shfl_xor_sync(0xffffffffu, v, o);
    return v;
}

// dot of one weight row (global, length C) with x (smem, 16B aligned).
// Whole warp participates; result valid on all lanes. KEEP THIS EXACT
// (reduction order determines bit-identity with the reference-passing run).
template <int C>
__device__ __forceinline__ float row_dot(const float* __restrict__ W,
                                         const float* __restrict__ x, int lane) {
    const float4* __restrict__ W4 = reinterpret_cast<const float4*>(W);
    const float4* __restrict__ x4 = reinterpret_cast<const float4*>(x);
    float s = 0.f;
#pragma unroll
    for (int c = 0; c < C / 4; c += 32) {
        float4 w = W4[c + lane];
        float4 xv = x4[c + lane];
        s += w.x * xv.x + w.y * xv.y + w.z * xv.z + w.w * xv.w;
    }
    return warp_reduce(s);
}

// LayerNorm over 256 elements, two-pass (matches ((x-mu)^2).mean()).
__device__ __forceinline__ void layernorm256(const float* __restrict__ y,
                                             float* __restrict__ out,
                                             const float* __restrict__ gma,
                                             const float* __restrict__ bta,
                                             int tid, float* red) {
    int w = tid >> 5, lane = tid & 31;
    if (w == 0) {
        float s = 0.f;
#pragma unroll
        for (int i = 0; i < 8; ++i) s += y[lane + 32 * i];
        s = warp_reduce(s);
        if (lane == 0) red[0] = s * (1.f / 256.f);
    }
    __syncthreads();
    float mu = red[0];
    if (w == 0) {
        float s = 0.f;
#pragma unroll
        for (int i = 0; i < 8; ++i) {
            float d = y[lane + 32 * i] - mu;
            s += d * d;
        }
        s = warp_reduce(s);
        if (lane == 0) red[1] = 1.f / sqrtf(s * (1.f / 256.f) + 1e-5f);
    }
    __syncthreads();
    float inv = red[1];
    if (tid < 256) out[tid] = (y[tid] - mu) * inv * gma[tid] + bta[tid];
    __syncthreads();
}

// Cluster-parallel recurrence: rows of every matvec split across CL CTAs,
// slices broadcast via L2-resident __device__ buffers + cluster barriers.
template <int CL>
__global__ void __launch_bounds__(1024, 1) seq_cluster_kernel(
    const float* __restrict__ gnn,
    const float* __restrict__ W1, const float* __restrict__ b1,
    const float* __restrict__ W2, const float* __restrict__ b2,
    const float* __restrict__ Wg, const float* __restrict__ bg,
    const float* __restrict__ Wv, const float* __restrict__ bv,
    const float* __restrict__ Wo, const float* __restrict__ bo,
    const float* __restrict__ Wf1, const float* __restrict__ bf1,
    const float* __restrict__ Wf2, const float* __restrict__ bf2,
    const float* __restrict__ ln1g, const float* __restrict__ ln1b,
    const float* __restrict__ ln2g, const float* __restrict__ ln2b) {
    constexpr int R_H1 = H1DIM / CL;  // h1 rows per CTA
    constexpr int R_SG = SG / CL;     // 256-row matvec rows per CTA
    constexpr int R_FF = DFF / CL;    // ff1 rows per CTA

    __shared__ __align__(16) float cat[H1DIM];  // [m(256); g(256)]
    __shared__ __align__(16) float h1s[H1DIM];
    __shared__ __align__(16) float hs[SG];
    __shared__ __align__(16) float gns[SG];
    __shared__ __align__(16) float vvs[SG];
    __shared__ __align__(16) float ys[SG];
    __shared__ __align__(16) float xs[SG];
    __shared__ __align__(16) float ff1s[DFF];
    __shared__ float red[2];

    int tid = threadIdx.x;
    int w = tid >> 5, lane = tid & 31;
    unsigned rank;
    asm("mov.u32 %0, %%cluster_ctarank;" : "=r"(rank));

    if (tid < 256) cat[256 + tid] = 0.f;  // g0 = 0
    __syncthreads();

    for (int t = 0; t < NSTEPS; ++t) {
        // m = gnn_embeds[t % 4096]
        if (tid < 256) cat[tid] = gnn[(size_t)(t & (NNODES - 1)) * SG + tid];
        __syncthreads();

        // stage 1: h1 slice = relu(W1 @ [m;g] + b1)
        for (int r = w; r < R_H1; r += 32) {
            int gr = rank * R_H1 + r;
            float s = row_dot<H1DIM>(W1 + (size_t)gr * H1DIM, cat, lane);
            if (lane == 0) g_h1[gr] = fmaxf(s + b1[gr], 0.f);
        }
        CLU_SYNC();
        for (int i = tid; i < H1DIM; i += 1024) h1s[i] = g_h1[i];
        __syncthreads();

        // stage 2: h slice = W2 @ h1 + b2  -> broadcast via g_h_all[t]
        float* gh = g_h_all + (size_t)t * SG;
        for (int r = w; r < R_SG; r += 32) {
            int gr = rank * R_SG + r;
            float s = row_dot<H1DIM>(W2 + (size_t)gr * H1DIM, h1s, lane);
            if (lane == 0) gh[gr] = s + b2[gr];
        }
        CLU_SYNC();
        for (int i = tid; i < SG; i += 1024) hs[i] = gh[i];
        __syncthreads();

        // stage 3: gnew slice = Wg @ h + bg
        for (int r = w; r < R_SG; r += 32) {
            int gr = rank * R_SG + r;
            float s = row_dot<SG>(Wg + (size_t)gr * SG, hs, lane);
            if (lane == 0) g_gnew[gr] = s + bg[gr];
        }
        CLU_SYNC();
        for (int i = tid; i < SG; i += 1024) gns[i] = g_gnew[i];
        __syncthreads();

        // stage 4: vv slice = Wv @ gnew + bv
        for (int r = w; r < R_SG; r += 32) {
            int gr = rank * R_SG + r;
            float s = row_dot<SG>(Wv + (size_t)gr * SG, gns, lane);
            if (lane == 0) g_vv[gr] = s + bv[gr];
        }
        CLU_SYNC();
        for (int i = tid; i < SG; i += 1024) vvs[i] = g_vv[i];
        __syncthreads();

        // stage 5: y1 slice = gnew + Wo @ vv + bo
        for (int r = w; r < R_SG; r += 32) {
            int gr = rank * R_SG + r;
            float s = row_dot<SG>(Wo + (size_t)gr * SG, vvs, lane);
            if (lane == 0) g_y1[gr] = gns[gr] + (s + bo[gr]);
        }
        CLU_SYNC();
        for (int i = tid; i < SG; i += 1024) ys[i] = g_y1[i];
        __syncthreads();

        // x = LN1(y1)  (redundant per CTA; no cluster sync needed)
        layernorm256(ys, xs, ln1g, ln1b, tid, red);

        // stage 6: ff1 slice = relu(Wf1 @ x + bf1)
        for (int r = w; r < R_FF; r += 32) {
            int gr = rank * R_FF + r;
            float s = row_dot<SG>(Wf1 + (size_t)gr * SG, xs, lane);
            if (lane == 0) g_ff1[gr] = fmaxf(s + bf1[gr], 0.f);
        }
        CLU_SYNC();
        for (int i = tid; i < DFF; i += 1024) ff1s[i] = g_ff1[i];
        __syncthreads();

        // stage 7: y2 slice = x + Wf2 @ ff1 + bf2
        for (int r = w; r < R_SG; r += 32) {
            int gr = rank * R_SG + r;
            float s = row_dot<DFF>(Wf2 + (size_t)gr * DFF, ff1s, lane);
            if (lane == 0) g_y2[gr] = xs[gr] + (s + bf2[gr]);
        }
        CLU_SYNC();
        for (int i = tid; i < SG; i += 1024) ys[i] = g_y2[i];
        __syncthreads();

        // g = LN2(y2) -> cat[256..511] (redundant per CTA)
        layernorm256(ys, cat + 256, ln2g, ln2b, tid, red);
    }
}

// Sampler: T=8 timesteps per block so Wr is read 1/8 as often.
// Per-row dot + sigmoid kept IDENTICAL to the bit-exact passing version.
#define SAMP_T 8
#define SAMP_THREADS 512
#define SAMP_SMEM ((SAMP_T * SG + SAMP_T * NROW) * 4)

__global__ void __launch_bounds__(SAMP_THREADS) sample_kernel8(
    const float* __restrict__ u,
    const float* __restrict__ Wr, const float* __restrict__ br,
    float* __restrict__ out) {
    extern __shared__ __align__(16) float sm[];
    float* hsm = sm;                 // [SAMP_T][SG]
    float* probs = sm + SAMP_T * SG; // [SAMP_T][NROW]
    __shared__ int cnt[SAMP_T][4];
    __shared__ int sel[SAMP_T];

    int tb = blockIdx.x * SAMP_T;
    int tid = threadIdx.x, w = tid >> 5, lane = tid & 31;

    for (int i = tid; i < SAMP_T * SG; i += SAMP_THREADS)
        hsm[i] = g_h_all[(size_t)tb * SG + i];
    if (tid < SAMP_T * 4) cnt[tid >> 2][tid & 3] = 0;
    __syncthreads();

    // probs[j][r] = sigmoid(Wr[r] . h_j + br[r]), warp-per-row, exact order
    for (int r = w; r < NROW; r += 16) {
        const float* Wrow = Wr + (size_t)r * SG;
        float brv = br[r];
#pragma unroll
        for (int j = 0; j < SAMP_T; ++j) {
            float s = row_dot<SG>(Wrow, hsm + j * SG, lane);
            if (lane == 0) {
                float z = s + brv;
                float p;
                if (z >= 0.f) {
                    p = 1.f / (1.f + expf(-z));
                } else {
                    float e = expf(z);
                    p = e / (1.f + e);
                }
                probs[j * NROW + r] = p;
            }
        }
    }
    __syncthreads();

#pragma unroll
    for (int j = 0; j < SAMP_T; ++j) {
        const float* __restrict__ ut = u + (size_t)(tb + j) * 4 * NROW;
        int c[4] = {0, 0, 0, 0};
#pragma unroll
        for (int k = 0; k < 4; ++k) {
#pragma unroll
            for (int i = 0; i < NROW / SAMP_THREADS; ++i) {
                int n = tid + SAMP_THREADS * i;
                c[k] += (ut[k * NROW + n] < probs[j * NROW + n]) ? 1 : 0;
            }
        }
#pragma unroll
        for (int k = 0; k < 4; ++k) {
            int s = c[k];
#pragma unroll
            for (int o = 16; o; o >>= 1) s += __shfl_xor_sync(0xffffffffu, s, o);
            if (lane == 0) atomicAdd(&cnt[j][k], s);
        }
    }
    __syncthreads();

    if (tid < SAMP_T) {
        int idx = 0;
        for (int k = 3; k >= 0; --k) {
            int ck = cnt[tid][k];
            bool valid = (ck == 0) || (ck >= 2 && ck <= 6);
            if (valid) idx = k;  // smallest valid k (argmax of bool)
        }
        sel[tid] = idx;
    }
    __syncthreads();

#pragma unroll
    for (int j = 0; j < SAMP_T; ++j) {
        const float* __restrict__ ut = u + (size_t)(tb + j) * 4 * NROW;
        int idx = sel[j];
#pragma unroll
        for (int i = 0; i < NROW / SAMP_THREADS; ++i) {
            int n = tid + SAMP_THREADS * i;
            out[(size_t)(tb + j) * NROW + n] =
                (ut[idx * NROW + n] < probs[j * NROW + n]) ? 1.f : 0.f;
        }
    }
}

extern "C" void kernel_launch(void* const* d_in, const int* in_sizes, int n_in,
                              void* d_out, int out_size) {
    (void)in_sizes; (void)n_in; (void)out_size;
    const float* gnn  = (const float*)d_in[0];
    // d_in[1] = b (unused dummy)
    const float* u    = (const float*)d_in[2];
    const float* W1   = (const float*)d_in[3];
    const float* b1   = (const float*)d_in[4];
    const float* W2   = (const float*)d_in[5];
    const float* b2   = (const float*)d_in[6];
    const float* Wr   = (const float*)d_in[7];
    const float* br   = (const float*)d_in[8];
    const float* Wg   = (const float*)d_in[9];
    const float* bg   = (const float*)d_in[10];
    const float* Wv   = (const float*)d_in[11];
    const float* bv   = (const float*)d_in[12];
    const float* Wo   = (const float*)d_in[13];
    const float* bo   = (const float*)d_in[14];
    const float* Wf1  = (const float*)d_in[15];
    const float* bf1  = (const float*)d_in[16];
    const float* Wf2  = (const float*)d_in[17];
    const float* bf2  = (const float*)d_in[18];
    const float* ln1g = (const float*)d_in[19];
    const float* ln1b = (const float*)d_in[20];
    const float* ln2g = (const float*)d_in[21];
    const float* ln2b = (const float*)d_in[22];

    // Prefer a 16-CTA cluster (nonportable); fall back to portable 8.
    cudaFuncSetAttribute(seq_cluster_kernel<16>,
                         cudaFuncAttributeNonPortableClusterSizeAllowed, 1);
    int maxC = 0;
    {
        cudaLaunchConfig_t q = {};
        q.gridDim = dim3(16, 1, 1);
        q.blockDim = dim3(1024, 1, 1);
        q.dynamicSmemBytes = 0;
        q.stream = 0;
        q.attrs = nullptr;
        q.numAttrs = 0;
        if (cudaOccupancyMaxPotentialClusterSize(&maxC, seq_cluster_kernel<16>, &q)
            != cudaSuccess)
            maxC = 8;
    }

    cudaError_t e = cudaErrorUnknown;
    if (maxC >= 16) {
        cudaLaunchConfig_t cfg = {};
        cfg.gridDim = dim3(16, 1, 1);
        cfg.blockDim = dim3(1024, 1, 1);
        cfg.dynamicSmemBytes = 0;
        cfg.stream = 0;
        cudaLaunchAttribute at[1];
        at[0].id = cudaLaunchAttributeClusterDimension;
        at[0].val.clusterDim.x = 16;
        at[0].val.clusterDim.y = 1;
        at[0].val.clusterDim.z = 1;
        cfg.attrs = at;
        cfg.numAttrs = 1;
        e = cudaLaunchKernelEx(&cfg, seq_cluster_kernel<16>,
                               gnn, W1, b1, W2, b2, Wg, bg, Wv, bv, Wo, bo,
                               Wf1, bf1, Wf2, bf2, ln1g, ln1b, ln2g, ln2b);
    }
    if (e != cudaSuccess) {
        cudaLaunchConfig_t cfg = {};
        cfg.gridDim = dim3(8, 1, 1);
        cfg.blockDim = dim3(1024, 1, 1);
        cfg.dynamicSmemBytes = 0;
        cfg.stream = 0;
        cudaLaunchAttribute at[1];
        at[0].id = cudaLaunchAttributeClusterDimension;
        at[0].val.clusterDim.x = 8;
        at[0].val.clusterDim.y = 1;
        at[0].val.clusterDim.z = 1;
        cfg.attrs = at;
        cfg.numAttrs = 1;
        cudaLaunchKernelEx(&cfg, seq_cluster_kernel<8>,
                           gnn, W1, b1, W2, b2, Wg, bg, Wv, bv, Wo, bo,
                           Wf1, bf1, Wf2, bf2, ln1g, ln1b, ln2g, ln2b);
    }

    cudaFuncSetAttribute(sample_kernel8,
                         cudaFuncAttributeMaxDynamicSharedMemorySize, SAMP_SMEM);
    sample_kernel8<<<NSTEPS / SAMP_T, SAMP_THREADS, SAMP_SMEM>>>(
        u, Wr, br, (float*)d_out);
}